// round 1
// baseline (speedup 1.0000x reference)
#include <cuda_runtime.h>
#include <cstddef>

// Problem constants
#define D_MODEL 2048
#define N_HEADS 16
#define D_HEAD  128
#define WINDOW  512
#define BATCH   2
#define SEQ     4096
#define NB      (SEQ / WINDOW)        // 8 windows per sequence
#define ROWS    (BATCH * SEQ)         // 8192
#define QKV_N   (3 * D_MODEL)         // 6144
#define SCALE_F 0.08838834764831845f  // 128^-0.5
#define LOG2E_F 1.4426950408889634f

// Scratch (allocation-free rule: __device__ globals)
__device__ float g_qkv[(size_t)ROWS * QKV_N];    // 201 MB
__device__ float g_att[(size_t)ROWS * D_MODEL];  //  67 MB

// ---------------------------------------------------------------------------
// SGEMM: C[M,N] = A[M,K] @ B[K,N] + bias[N]   (all fp32, row-major,
// M%128==0, N%128==0, K%16==0). 256 threads, 128x128 tile, 8x8 per thread,
// double-buffered smem.
// ---------------------------------------------------------------------------
#define BM 128
#define BN 128
#define BK 16
#define TM 8
#define TN 8

__global__ __launch_bounds__(256, 2)
void gemm_bias_kernel(const float* __restrict__ A, const float* __restrict__ Bm,
                      const float* __restrict__ bias, float* __restrict__ C,
                      int M, int N, int K)
{
    __shared__ float As[2][BK][BM + 4];   // A tile stored transposed (k-major)
    __shared__ float Bs[2][BK][BN];

    const int tid = threadIdx.x;
    const int bm = blockIdx.y * BM;
    const int bn = blockIdx.x * BN;

    // A tile load mapping: 128 rows x 16 cols = 512 float4, 2 per thread
    const int a_row = tid >> 2;           // 0..63
    const int a_col = (tid & 3) << 2;     // 0,4,8,12
    // B tile load mapping: 16 rows x 128 cols = 512 float4, 2 per thread
    const int b_row = tid >> 5;           // 0..7
    const int b_col = (tid & 31) << 2;    // 0..124

    // compute mapping: 16x16 thread grid, 8x8 micro tile
    const int tr = (tid >> 4) * TM;
    const int tc = (tid & 15) * TN;

    float acc[TM][TN];
    #pragma unroll
    for (int i = 0; i < TM; i++)
        #pragma unroll
        for (int j = 0; j < TN; j++) acc[i][j] = 0.0f;

    const float* Aptr = A + (size_t)bm * K;
    const float* Bptr = Bm + bn;

    float4 a_reg[2], b_reg[2];

    // prefetch k-tile 0
    #pragma unroll
    for (int i = 0; i < 2; i++) {
        a_reg[i] = *(const float4*)(Aptr + (size_t)(a_row + i * 64) * K + a_col);
        b_reg[i] = *(const float4*)(Bptr + (size_t)(b_row + i * 8) * N + b_col);
    }
    #pragma unroll
    for (int i = 0; i < 2; i++) {
        As[0][a_col + 0][a_row + i * 64] = a_reg[i].x;
        As[0][a_col + 1][a_row + i * 64] = a_reg[i].y;
        As[0][a_col + 2][a_row + i * 64] = a_reg[i].z;
        As[0][a_col + 3][a_row + i * 64] = a_reg[i].w;
        *(float4*)&Bs[0][b_row + i * 8][b_col] = b_reg[i];
    }
    __syncthreads();

    const int nk = K / BK;
    for (int kt = 0; kt < nk; kt++) {
        const int cur = kt & 1;
        if (kt + 1 < nk) {
            const int k0 = (kt + 1) * BK;
            #pragma unroll
            for (int i = 0; i < 2; i++) {
                a_reg[i] = *(const float4*)(Aptr + (size_t)(a_row + i * 64) * K + k0 + a_col);
                b_reg[i] = *(const float4*)(Bptr + (size_t)(k0 + b_row + i * 8) * N + b_col);
            }
        }
        #pragma unroll
        for (int kk = 0; kk < BK; kk++) {
            float af[TM], bf[TN];
            #pragma unroll
            for (int i = 0; i < TM; i += 4)
                *(float4*)&af[i] = *(const float4*)&As[cur][kk][tr + i];
            #pragma unroll
            for (int j = 0; j < TN; j += 4)
                *(float4*)&bf[j] = *(const float4*)&Bs[cur][kk][tc + j];
            #pragma unroll
            for (int i = 0; i < TM; i++)
                #pragma unroll
                for (int j = 0; j < TN; j++)
                    acc[i][j] = fmaf(af[i], bf[j], acc[i][j]);
        }
        if (kt + 1 < nk) {
            const int nxt = cur ^ 1;
            #pragma unroll
            for (int i = 0; i < 2; i++) {
                As[nxt][a_col + 0][a_row + i * 64] = a_reg[i].x;
                As[nxt][a_col + 1][a_row + i * 64] = a_reg[i].y;
                As[nxt][a_col + 2][a_row + i * 64] = a_reg[i].z;
                As[nxt][a_col + 3][a_row + i * 64] = a_reg[i].w;
                *(float4*)&Bs[nxt][b_row + i * 8][b_col] = b_reg[i];
            }
            __syncthreads();
        }
    }

    // epilogue: add bias, vectorized stores
    float bv[TN];
    #pragma unroll
    for (int j = 0; j < TN; j++) bv[j] = bias[bn + tc + j];

    #pragma unroll
    for (int i = 0; i < TM; i++) {
        const size_t row = (size_t)(bm + tr + i);
        float4 o0, o1;
        o0.x = acc[i][0] + bv[0]; o0.y = acc[i][1] + bv[1];
        o0.z = acc[i][2] + bv[2]; o0.w = acc[i][3] + bv[3];
        o1.x = acc[i][4] + bv[4]; o1.y = acc[i][5] + bv[5];
        o1.z = acc[i][6] + bv[6]; o1.w = acc[i][7] + bv[7];
        *(float4*)(C + row * N + bn + tc)     = o0;
        *(float4*)(C + row * N + bn + tc + 4) = o1;
    }
}

// ---------------------------------------------------------------------------
// Windowed causal flash attention.
// Grid: (W/64 q-tiles, NB windows, B*H). 256 threads.
// Each block: one 64-row q-tile of one (batch, head, window). Iterates K/V
// tiles j=0..qb (causal block skipping), online softmax in registers.
// Thread map for the 64x64 score tile: (tid>>4) -> 4 rows, (tid&15) -> 4 cols.
// O accumulator: 4 rows x 8 cols per thread (16 col-threads x 8 = 128 dims).
// ---------------------------------------------------------------------------
#define TQ 64
#define TK 64
#define QPAD 132    // 128 + 4 (keeps float4 alignment: 132 % 4 == 0)
#define PPAD 68

#define ATTN_SMEM ((TQ * QPAD + TK * QPAD + TQ * PPAD) * (int)sizeof(float))  // 84992 B

__device__ __forceinline__ void attn_load_tile(float* dst, const float* src)
{
    // 64 rows x 128 floats, src row stride QKV_N, dst row stride QPAD
    #pragma unroll
    for (int i = 0; i < 8; i++) {
        const int lin = threadIdx.x + i * 256;   // 0..2047
        const int r = lin >> 5;
        const int c = (lin & 31) << 2;
        *(float4*)&dst[r * QPAD + c] = *(const float4*)&src[(size_t)r * QKV_N + c];
    }
}

__global__ __launch_bounds__(256)
void attn_kernel(const float* __restrict__ qkv, float* __restrict__ out)
{
    extern __shared__ float sm[];
    float* Qs  = sm;                       // TQ x QPAD
    float* KVs = Qs + TQ * QPAD;           // TK x QPAD (K, then reused for V)
    float* Ps  = KVs + TK * QPAD;          // TQ x PPAD

    const int tid = threadIdx.x;
    const int qb = blockIdx.x;             // q-tile within window (0..7)
    const int n  = blockIdx.y;             // window index (0..7)
    const int bh = blockIdx.z;             // b*16 + h
    const int b  = bh >> 4;
    const int h  = bh & 15;

    const size_t row0 = (size_t)b * SEQ + (size_t)n * WINDOW;
    const float* qbase = qkv + row0 * QKV_N + h * D_HEAD;
    const float* kbase = qbase + D_MODEL;
    const float* vbase = qbase + 2 * D_MODEL;

    // load Q tile (rows qb*64 .. qb*64+63)
    attn_load_tile(Qs, qbase + (size_t)(qb * TQ) * QKV_N);

    const int tr = tid >> 4;   // 0..15 -> rows tr*4 + i
    const int tc = tid & 15;   // 0..15 -> score cols tc*4 + j, O cols tc*8 + j

    float m[4], l[4], o[4][8];
    #pragma unroll
    for (int i = 0; i < 4; i++) {
        m[i] = -1e30f; l[i] = 0.0f;
        #pragma unroll
        for (int j = 0; j < 8; j++) o[i][j] = 0.0f;
    }

    for (int jt = 0; jt <= qb; jt++) {
        __syncthreads();  // prior iteration's V/P reads complete
        attn_load_tile(KVs, kbase + (size_t)(jt * TK) * QKV_N);
        __syncthreads();

        // S = Q @ K^T (64x64), 4x4 per thread
        float s[4][4];
        #pragma unroll
        for (int i = 0; i < 4; i++)
            #pragma unroll
            for (int j = 0; j < 4; j++) s[i][j] = 0.0f;

        #pragma unroll 4
        for (int d = 0; d < D_HEAD; d += 4) {
            float4 q4[4], k4[4];
            #pragma unroll
            for (int i = 0; i < 4; i++)
                q4[i] = *(const float4*)&Qs[(tr * 4 + i) * QPAD + d];
            #pragma unroll
            for (int j = 0; j < 4; j++)
                k4[j] = *(const float4*)&KVs[(tc * 4 + j) * QPAD + d];
            #pragma unroll
            for (int i = 0; i < 4; i++)
                #pragma unroll
                for (int j = 0; j < 4; j++) {
                    s[i][j] = fmaf(q4[i].x, k4[j].x, s[i][j]);
                    s[i][j] = fmaf(q4[i].y, k4[j].y, s[i][j]);
                    s[i][j] = fmaf(q4[i].z, k4[j].z, s[i][j]);
                    s[i][j] = fmaf(q4[i].w, k4[j].w, s[i][j]);
                }
        }

        // scale + causal mask (within-window indices; jt < qb is never masked)
        #pragma unroll
        for (int i = 0; i < 4; i++) {
            const int qg = qb * TQ + tr * 4 + i;
            #pragma unroll
            for (int j = 0; j < 4; j++) {
                float sv = s[i][j] * SCALE_F;
                if (jt * TK + tc * 4 + j > qg) sv = -1e30f;
                s[i][j] = sv;
            }
        }

        // online softmax update, row reductions across the 16 col-lanes
        #pragma unroll
        for (int i = 0; i < 4; i++) {
            float mt = fmaxf(fmaxf(s[i][0], s[i][1]), fmaxf(s[i][2], s[i][3]));
            #pragma unroll
            for (int off = 1; off < 16; off <<= 1)
                mt = fmaxf(mt, __shfl_xor_sync(0xffffffffu, mt, off));
            const float mn = fmaxf(m[i], mt);
            const float f = exp2f((m[i] - mn) * LOG2E_F);
            float rs = 0.0f;
            #pragma unroll
            for (int j = 0; j < 4; j++) {
                const float p = exp2f((s[i][j] - mn) * LOG2E_F);
                s[i][j] = p;
                rs += p;
            }
            #pragma unroll
            for (int off = 1; off < 16; off <<= 1)
                rs += __shfl_xor_sync(0xffffffffu, rs, off);
            l[i] = l[i] * f + rs;
            m[i] = mn;
            #pragma unroll
            for (int j = 0; j < 8; j++) o[i][j] *= f;
            #pragma unroll
            for (int j = 0; j < 4; j++)
                Ps[(tr * 4 + i) * PPAD + tc * 4 + j] = s[i][j];
        }

        __syncthreads();  // K reads + P writes complete
        attn_load_tile(KVs, vbase + (size_t)(jt * TK) * QKV_N);
        __syncthreads();

        // O += P @ V
        #pragma unroll 4
        for (int kk = 0; kk < TK; kk++) {
            const float4 v0 = *(const float4*)&KVs[kk * QPAD + tc * 8];
            const float4 v1 = *(const float4*)&KVs[kk * QPAD + tc * 8 + 4];
            float pv[4];
            #pragma unroll
            for (int i = 0; i < 4; i++) pv[i] = Ps[(tr * 4 + i) * PPAD + kk];
            #pragma unroll
            for (int i = 0; i < 4; i++) {
                o[i][0] = fmaf(pv[i], v0.x, o[i][0]);
                o[i][1] = fmaf(pv[i], v0.y, o[i][1]);
                o[i][2] = fmaf(pv[i], v0.z, o[i][2]);
                o[i][3] = fmaf(pv[i], v0.w, o[i][3]);
                o[i][4] = fmaf(pv[i], v1.x, o[i][4]);
                o[i][5] = fmaf(pv[i], v1.y, o[i][5]);
                o[i][6] = fmaf(pv[i], v1.z, o[i][6]);
                o[i][7] = fmaf(pv[i], v1.w, o[i][7]);
            }
        }
    }

    // normalize and write out[b, n*W + q, h*128 + d]  (head-interleaved (B,S,D))
    #pragma unroll
    for (int i = 0; i < 4; i++) {
        const float inv = 1.0f / l[i];
        const size_t grow = row0 + (size_t)(qb * TQ + tr * 4 + i);
        float4 o0, o1;
        o0.x = o[i][0] * inv; o0.y = o[i][1] * inv;
        o0.z = o[i][2] * inv; o0.w = o[i][3] * inv;
        o1.x = o[i][4] * inv; o1.y = o[i][5] * inv;
        o1.z = o[i][6] * inv; o1.w = o[i][7] * inv;
        float* op = out + grow * D_MODEL + h * D_HEAD + tc * 8;
        *(float4*)op       = o0;
        *(float4*)(op + 4) = o1;
    }
}

// ---------------------------------------------------------------------------
extern "C" void kernel_launch(void* const* d_in, const int* in_sizes, int n_in,
                              void* d_out, int out_size)
{
    const float* x    = (const float*)d_in[0];
    const float* Wqkv = (const float*)d_in[1];
    const float* bqkv = (const float*)d_in[2];
    const float* Wout = (const float*)d_in[3];
    const float* bout = (const float*)d_in[4];
    float* out = (float*)d_out;

    float *qkv, *att;
    cudaGetSymbolAddress((void**)&qkv, g_qkv);
    cudaGetSymbolAddress((void**)&att, g_att);

    cudaFuncSetAttribute(attn_kernel,
                         cudaFuncAttributeMaxDynamicSharedMemorySize, ATTN_SMEM);

    // 1) QKV projection: g_qkv = x @ W_qkv + b_qkv
    {
        dim3 grid(QKV_N / BN, ROWS / BM);
        gemm_bias_kernel<<<grid, 256>>>(x, Wqkv, bqkv, qkv, ROWS, QKV_N, D_MODEL);
    }
    // 2) windowed causal attention -> g_att (head-interleaved (B,S,D))
    {
        dim3 grid(WINDOW / TQ, NB, BATCH * N_HEADS);
        attn_kernel<<<grid, 256, ATTN_SMEM>>>(qkv, att);
    }
    // 3) output projection: out = g_att @ W_out + b_out
    {
        dim3 grid(D_MODEL / BN, ROWS / BM);
        gemm_bias_kernel<<<grid, 256>>>(att, Wout, bout, out, ROWS, D_MODEL, D_MODEL);
    }
}

// round 3
// speedup vs baseline: 2.1288x; 2.1288x over previous
#include <cuda_runtime.h>
#include <cuda_bf16.h>
#include <cstdint>
#include <cstddef>

// Problem constants
#define D_MODEL 2048
#define N_HEADS 16
#define D_HEAD  128
#define WINDOW  512
#define BATCH   2
#define SEQ     4096
#define NB      (SEQ / WINDOW)
#define ROWS    (BATCH * SEQ)         // 8192
#define QKV_N   (3 * D_MODEL)         // 6144
#define KDIM    D_MODEL               // 2048
#define SCALE_F 0.08838834764831845f
#define LOG2E_F 1.4426950408889634f

// ---------------------------------------------------------------------------
// Scratch (__device__ globals; no allocation allowed)
// ---------------------------------------------------------------------------
__device__ float          g_qkv[(size_t)ROWS * QKV_N];
__device__ float          g_att[(size_t)ROWS * D_MODEL];
__device__ __nv_bfloat16  g_ahi[(size_t)ROWS * KDIM];
__device__ __nv_bfloat16  g_alo[(size_t)ROWS * KDIM];
__device__ __nv_bfloat16  g_wqkv_hi[(size_t)QKV_N * KDIM];
__device__ __nv_bfloat16  g_wqkv_lo[(size_t)QKV_N * KDIM];
__device__ __nv_bfloat16  g_wout_hi[(size_t)D_MODEL * KDIM];
__device__ __nv_bfloat16  g_wout_lo[(size_t)D_MODEL * KDIM];

// ---------------------------------------------------------------------------
// Baseline-ISA helpers (NO tcgen05 — ptxas target is compute_103, not 103a)
// ---------------------------------------------------------------------------
__device__ __forceinline__ uint32_t smem_u32(const void* p) {
    uint32_t a;
    asm("{ .reg .u64 t; cvta.to.shared.u64 t, %1; cvt.u32.u64 %0, t; }" : "=r"(a) : "l"(p));
    return a;
}
#define CP_ASYNC16(dst, src) \
    asm volatile("cp.async.cg.shared.global [%0], [%1], 16;" :: "r"(dst), "l"(src))
#define CP_COMMIT()  asm volatile("cp.async.commit_group;" ::: "memory")
#define CP_WAIT1()   asm volatile("cp.async.wait_group 1;" ::: "memory")

__device__ __forceinline__ void ldmx4(uint32_t* r, uint32_t addr) {
    asm volatile("ldmatrix.sync.aligned.m8n8.x4.shared.b16 {%0,%1,%2,%3}, [%4];"
                 : "=r"(r[0]), "=r"(r[1]), "=r"(r[2]), "=r"(r[3]) : "r"(addr));
}
__device__ __forceinline__ void mma_bf16(float* d, const uint32_t* a, const uint32_t* b) {
    asm volatile("mma.sync.aligned.m16n8k16.row.col.f32.bf16.bf16.f32 "
                 "{%0,%1,%2,%3}, {%4,%5,%6,%7}, {%8,%9}, {%0,%1,%2,%3};"
                 : "+f"(d[0]), "+f"(d[1]), "+f"(d[2]), "+f"(d[3])
                 : "r"(a[0]), "r"(a[1]), "r"(a[2]), "r"(a[3]), "r"(b[0]), "r"(b[1]));
}

// ---------------------------------------------------------------------------
// Conversion kernels: fp32 -> (bf16 hi, bf16 lo) split
// ---------------------------------------------------------------------------
__global__ void split_hilo(const float* __restrict__ in, __nv_bfloat16* __restrict__ hi,
                           __nv_bfloat16* __restrict__ lo, int n4)
{
    int i = blockIdx.x * blockDim.x + threadIdx.x;
    if (i >= n4) return;
    float4 v = ((const float4*)in)[i];
    __nv_bfloat16 h0 = __float2bfloat16(v.x), h1 = __float2bfloat16(v.y);
    __nv_bfloat16 h2 = __float2bfloat16(v.z), h3 = __float2bfloat16(v.w);
    __nv_bfloat162* hp = (__nv_bfloat162*)hi;
    __nv_bfloat162* lp = (__nv_bfloat162*)lo;
    hp[i * 2 + 0] = __nv_bfloat162(h0, h1);
    hp[i * 2 + 1] = __nv_bfloat162(h2, h3);
    lp[i * 2 + 0] = __nv_bfloat162(__float2bfloat16(v.x - __bfloat162float(h0)),
                                   __float2bfloat16(v.y - __bfloat162float(h1)));
    lp[i * 2 + 1] = __nv_bfloat162(__float2bfloat16(v.z - __bfloat162float(h2)),
                                   __float2bfloat16(v.w - __bfloat162float(h3)));
}

// W[K,N] fp32 -> Wt hi/lo [N,K] bf16 (transpose + split)
__global__ void transpose_split(const float* __restrict__ W, __nv_bfloat16* __restrict__ hi,
                                __nv_bfloat16* __restrict__ lo, int K, int N)
{
    __shared__ float t[32][33];
    const int n0 = blockIdx.x * 32, k0 = blockIdx.y * 32;
    const int tx = threadIdx.x, ty = threadIdx.y;  // 32 x 8
    #pragma unroll
    for (int i = 0; i < 4; i++)
        t[ty + i * 8][tx] = W[(size_t)(k0 + ty + i * 8) * N + n0 + tx];
    __syncthreads();
    #pragma unroll
    for (int i = 0; i < 4; i++) {
        float v = t[tx][ty + i * 8];
        size_t o = (size_t)(n0 + ty + i * 8) * K + k0 + tx;
        __nv_bfloat16 h = __float2bfloat16(v);
        hi[o] = h;
        lo[o] = __float2bfloat16(v - __bfloat162float(h));
    }
}

// ---------------------------------------------------------------------------
// mma.sync split-bf16 GEMM: C[M,N] = A @ Wt^T + bias
//   3-term emulation: Ahi*Bhi + Ahi*Blo + Alo*Bhi, fp32 accumulators.
//   CTA tile 128x128, 8 warps (each 64x32), BK=32, double-buffered cp.async.
//   Smem rows padded to 40 bf16 (80 B) -> conflict-free ldmatrix.
// ---------------------------------------------------------------------------
#define GBM 128
#define GBN 128
#define GBK 32
#define LDT 40                        // padded row stride in bf16 elems
#define BUF_B (128 * LDT * 2)         // 10240 B per hi/lo tile
#define STAGE_B (4 * BUF_B)           // AHI, ALO, BHI, BLO = 40960 B
#define GEMM_SMEM (2 * STAGE_B)       // 81920 B

__device__ __forceinline__ void load_stage(
    uint32_t sb, uint32_t stage,
    const __nv_bfloat16* __restrict__ ahi, const __nv_bfloat16* __restrict__ alo,
    const __nv_bfloat16* __restrict__ bhi, const __nv_bfloat16* __restrict__ blo,
    int bm, int bn, int k0, int tid)
{
    // 4 buffers x 128 rows x 4 chunks of 16B = 2048 cp.async; 8 per thread
    #pragma unroll
    for (int it = 0; it < 8; it++) {
        const int c = tid + it * 256;
        const int buf = c >> 9;            // 0:AHI 1:ALO 2:BHI 3:BLO
        const int row = (c >> 2) & 127;
        const int kc = c & 3;
        const __nv_bfloat16* src;
        int grow;
        if (buf == 0)      { src = ahi; grow = bm + row; }
        else if (buf == 1) { src = alo; grow = bm + row; }
        else if (buf == 2) { src = bhi; grow = bn + row; }
        else               { src = blo; grow = bn + row; }
        const uint32_t dst = sb + stage + buf * BUF_B + row * (LDT * 2) + kc * 16;
        CP_ASYNC16(dst, src + (size_t)grow * KDIM + k0 + kc * 8);
    }
}

__global__ __launch_bounds__(256, 1)
void gemm_mma_kernel(const __nv_bfloat16* __restrict__ ahi, const __nv_bfloat16* __restrict__ alo,
                     const __nv_bfloat16* __restrict__ bhi, const __nv_bfloat16* __restrict__ blo,
                     const float* __restrict__ bias, float* __restrict__ C, int N)
{
    extern __shared__ char smem[];
    const uint32_t sb = smem_u32(smem);
    const int tid = threadIdx.x;
    const int wid = tid >> 5;
    const int lane = tid & 31;
    const int bm = blockIdx.y * GBM;
    const int bn = blockIdx.x * GBN;
    const int warp_m = (wid >> 2) * 64;   // 0 or 64
    const int warp_n = (wid & 3) * 32;    // 0,32,64,96

    float d[4][4][4];
    #pragma unroll
    for (int i = 0; i < 4; i++)
        #pragma unroll
        for (int j = 0; j < 4; j++)
            #pragma unroll
            for (int r = 0; r < 4; r++) d[i][j][r] = 0.0f;

    const int nk = KDIM / GBK;  // 64

    load_stage(sb, 0, ahi, alo, bhi, blo, bm, bn, 0, tid);
    CP_COMMIT();
    load_stage(sb, STAGE_B, ahi, alo, bhi, blo, bm, bn, GBK, tid);
    CP_COMMIT();
    CP_WAIT1();
    __syncthreads();

    for (int kt = 0; kt < nk; kt++) {
        const uint32_t stage = (kt & 1) ? STAGE_B : 0u;

        #pragma unroll
        for (int k16 = 0; k16 < 2; k16++) {
            uint32_t ra[2][4][4];   // [hi/lo][mf][reg]
            uint32_t rb[2][2][4];   // [hi/lo][nf-pair][reg]
            #pragma unroll
            for (int hl = 0; hl < 2; hl++) {
                const uint32_t abase = sb + stage + hl * BUF_B;
                #pragma unroll
                for (int mf = 0; mf < 4; mf++) {
                    const int row = warp_m + mf * 16 + (lane & 15);
                    const int col = ((lane >> 4) << 3) + k16 * 16;
                    ldmx4(ra[hl][mf], abase + row * (LDT * 2) + col * 2);
                }
                const uint32_t bbase = sb + stage + (2 + hl) * BUF_B;
                #pragma unroll
                for (int nf2 = 0; nf2 < 2; nf2++) {
                    const int row = warp_n + nf2 * 16 + ((lane >> 4) << 3) + (lane & 7);
                    const int col = (((lane >> 3) & 1) << 3) + k16 * 16;
                    ldmx4(rb[hl][nf2], bbase + row * (LDT * 2) + col * 2);
                }
            }
            // 3 terms: hi*hi, hi*lo, lo*hi
            #pragma unroll
            for (int t = 0; t < 3; t++) {
                const int ah = (t == 2) ? 1 : 0;
                const int bh = (t == 1) ? 1 : 0;
                #pragma unroll
                for (int mf = 0; mf < 4; mf++)
                    #pragma unroll
                    for (int nf = 0; nf < 4; nf++)
                        mma_bf16(d[mf][nf], ra[ah][mf], &rb[bh][nf >> 1][(nf & 1) * 2]);
            }
        }

        __syncthreads();  // all warps done reading `stage`
        if (kt + 2 < nk)
            load_stage(sb, stage, ahi, alo, bhi, blo, bm, bn, (kt + 2) * GBK, tid);
        CP_COMMIT();
        CP_WAIT1();       // next stage fully landed
        __syncthreads();
    }

    // epilogue: accum + bias -> gmem (float2 per thread per frag row)
    #pragma unroll
    for (int nf = 0; nf < 4; nf++) {
        const int c0 = bn + warp_n + nf * 8 + (lane & 3) * 2;
        const float b0 = bias[c0], b1 = bias[c0 + 1];
        #pragma unroll
        for (int mf = 0; mf < 4; mf++) {
            const int r0 = bm + warp_m + mf * 16 + (lane >> 2);
            float2 v0, v1;
            v0.x = d[mf][nf][0] + b0; v0.y = d[mf][nf][1] + b1;
            v1.x = d[mf][nf][2] + b0; v1.y = d[mf][nf][3] + b1;
            *(float2*)&C[(size_t)r0 * N + c0]       = v0;
            *(float2*)&C[(size_t)(r0 + 8) * N + c0] = v1;
        }
    }
}

// ---------------------------------------------------------------------------
// Windowed causal flash attention (fp32 SIMT, proven in R1)
// ---------------------------------------------------------------------------
#define TQ 64
#define TK 64
#define QPAD 132
#define PPAD 68
#define ATTN_SMEM ((TQ * QPAD + TK * QPAD + TQ * PPAD) * (int)sizeof(float))

__device__ __forceinline__ void attn_load_tile(float* dst, const float* src)
{
    #pragma unroll
    for (int i = 0; i < 8; i++) {
        const int lin = threadIdx.x + i * 256;
        const int r = lin >> 5;
        const int c = (lin & 31) << 2;
        *(float4*)&dst[r * QPAD + c] = *(const float4*)&src[(size_t)r * QKV_N + c];
    }
}

__global__ __launch_bounds__(256)
void attn_kernel(const float* __restrict__ qkv, float* __restrict__ out)
{
    extern __shared__ float sm[];
    float* Qs  = sm;
    float* KVs = Qs + TQ * QPAD;
    float* Ps  = KVs + TK * QPAD;

    const int tid = threadIdx.x;
    const int qb = blockIdx.x;
    const int n  = blockIdx.y;
    const int bh = blockIdx.z;
    const int b  = bh >> 4;
    const int h  = bh & 15;

    const size_t row0 = (size_t)b * SEQ + (size_t)n * WINDOW;
    const float* qbase = qkv + row0 * QKV_N + h * D_HEAD;
    const float* kbase = qbase + D_MODEL;
    const float* vbase = qbase + 2 * D_MODEL;

    attn_load_tile(Qs, qbase + (size_t)(qb * TQ) * QKV_N);

    const int tr = tid >> 4;
    const int tc = tid & 15;

    float m[4], l[4], o[4][8];
    #pragma unroll
    for (int i = 0; i < 4; i++) {
        m[i] = -1e30f; l[i] = 0.0f;
        #pragma unroll
        for (int j = 0; j < 8; j++) o[i][j] = 0.0f;
    }

    for (int jt = 0; jt <= qb; jt++) {
        __syncthreads();
        attn_load_tile(KVs, kbase + (size_t)(jt * TK) * QKV_N);
        __syncthreads();

        float s[4][4];
        #pragma unroll
        for (int i = 0; i < 4; i++)
            #pragma unroll
            for (int j = 0; j < 4; j++) s[i][j] = 0.0f;

        #pragma unroll 4
        for (int d = 0; d < D_HEAD; d += 4) {
            float4 q4[4], k4[4];
            #pragma unroll
            for (int i = 0; i < 4; i++)
                q4[i] = *(const float4*)&Qs[(tr * 4 + i) * QPAD + d];
            #pragma unroll
            for (int j = 0; j < 4; j++)
                k4[j] = *(const float4*)&KVs[(tc * 4 + j) * QPAD + d];
            #pragma unroll
            for (int i = 0; i < 4; i++)
                #pragma unroll
                for (int j = 0; j < 4; j++) {
                    s[i][j] = fmaf(q4[i].x, k4[j].x, s[i][j]);
                    s[i][j] = fmaf(q4[i].y, k4[j].y, s[i][j]);
                    s[i][j] = fmaf(q4[i].z, k4[j].z, s[i][j]);
                    s[i][j] = fmaf(q4[i].w, k4[j].w, s[i][j]);
                }
        }

        #pragma unroll
        for (int i = 0; i < 4; i++) {
            const int qg = qb * TQ + tr * 4 + i;
            #pragma unroll
            for (int j = 0; j < 4; j++) {
                float sv = s[i][j] * SCALE_F;
                if (jt * TK + tc * 4 + j > qg) sv = -1e30f;
                s[i][j] = sv;
            }
        }

        #pragma unroll
        for (int i = 0; i < 4; i++) {
            float mt = fmaxf(fmaxf(s[i][0], s[i][1]), fmaxf(s[i][2], s[i][3]));
            #pragma unroll
            for (int off = 1; off < 16; off <<= 1)
                mt = fmaxf(mt, __shfl_xor_sync(0xffffffffu, mt, off));
            const float mn = fmaxf(m[i], mt);
            const float f = exp2f((m[i] - mn) * LOG2E_F);
            float rs = 0.0f;
            #pragma unroll
            for (int j = 0; j < 4; j++) {
                const float p = exp2f((s[i][j] - mn) * LOG2E_F);
                s[i][j] = p;
                rs += p;
            }
            #pragma unroll
            for (int off = 1; off < 16; off <<= 1)
                rs += __shfl_xor_sync(0xffffffffu, rs, off);
            l[i] = l[i] * f + rs;
            m[i] = mn;
            #pragma unroll
            for (int j = 0; j < 8; j++) o[i][j] *= f;
            #pragma unroll
            for (int j = 0; j < 4; j++)
                Ps[(tr * 4 + i) * PPAD + tc * 4 + j] = s[i][j];
        }

        __syncthreads();
        attn_load_tile(KVs, vbase + (size_t)(jt * TK) * QKV_N);
        __syncthreads();

        #pragma unroll 4
        for (int kk = 0; kk < TK; kk++) {
            const float4 v0 = *(const float4*)&KVs[kk * QPAD + tc * 8];
            const float4 v1 = *(const float4*)&KVs[kk * QPAD + tc * 8 + 4];
            float pv[4];
            #pragma unroll
            for (int i = 0; i < 4; i++) pv[i] = Ps[(tr * 4 + i) * PPAD + kk];
            #pragma unroll
            for (int i = 0; i < 4; i++) {
                o[i][0] = fmaf(pv[i], v0.x, o[i][0]);
                o[i][1] = fmaf(pv[i], v0.y, o[i][1]);
                o[i][2] = fmaf(pv[i], v0.z, o[i][2]);
                o[i][3] = fmaf(pv[i], v0.w, o[i][3]);
                o[i][4] = fmaf(pv[i], v1.x, o[i][4]);
                o[i][5] = fmaf(pv[i], v1.y, o[i][5]);
                o[i][6] = fmaf(pv[i], v1.z, o[i][6]);
                o[i][7] = fmaf(pv[i], v1.w, o[i][7]);
            }
        }
    }

    #pragma unroll
    for (int i = 0; i < 4; i++) {
        const float inv = 1.0f / l[i];
        const size_t grow = row0 + (size_t)(qb * TQ + tr * 4 + i);
        float4 o0, o1;
        o0.x = o[i][0] * inv; o0.y = o[i][1] * inv;
        o0.z = o[i][2] * inv; o0.w = o[i][3] * inv;
        o1.x = o[i][4] * inv; o1.y = o[i][5] * inv;
        o1.z = o[i][6] * inv; o1.w = o[i][7] * inv;
        float* op = out + grow * D_MODEL + h * D_HEAD + tc * 8;
        *(float4*)op       = o0;
        *(float4*)(op + 4) = o1;
    }
}

// ---------------------------------------------------------------------------
extern "C" void kernel_launch(void* const* d_in, const int* in_sizes, int n_in,
                              void* d_out, int out_size)
{
    const float* x    = (const float*)d_in[0];
    const float* Wqkv = (const float*)d_in[1];
    const float* bqkv = (const float*)d_in[2];
    const float* Wout = (const float*)d_in[3];
    const float* bout = (const float*)d_in[4];
    float* out = (float*)d_out;

    float *qkv, *att;
    __nv_bfloat16 *ahi, *alo, *wqh, *wql, *woh, *wol;
    cudaGetSymbolAddress((void**)&qkv, g_qkv);
    cudaGetSymbolAddress((void**)&att, g_att);
    cudaGetSymbolAddress((void**)&ahi, g_ahi);
    cudaGetSymbolAddress((void**)&alo, g_alo);
    cudaGetSymbolAddress((void**)&wqh, g_wqkv_hi);
    cudaGetSymbolAddress((void**)&wql, g_wqkv_lo);
    cudaGetSymbolAddress((void**)&woh, g_wout_hi);
    cudaGetSymbolAddress((void**)&wol, g_wout_lo);

    cudaFuncSetAttribute(attn_kernel,
                         cudaFuncAttributeMaxDynamicSharedMemorySize, ATTN_SMEM);
    cudaFuncSetAttribute(gemm_mma_kernel,
                         cudaFuncAttributeMaxDynamicSharedMemorySize, GEMM_SMEM);

    // weight conversions (transpose + hi/lo split)
    transpose_split<<<dim3(QKV_N / 32, KDIM / 32), dim3(32, 8)>>>(Wqkv, wqh, wql, KDIM, QKV_N);
    transpose_split<<<dim3(D_MODEL / 32, KDIM / 32), dim3(32, 8)>>>(Wout, woh, wol, KDIM, D_MODEL);

    // x -> hi/lo
    {
        const int n4 = ROWS * D_MODEL / 4;
        split_hilo<<<(n4 + 255) / 256, 256>>>(x, ahi, alo, n4);
    }
    // 1) QKV projection (mma.sync split-bf16): qkv = x @ W_qkv + b_qkv
    gemm_mma_kernel<<<dim3(QKV_N / GBN, ROWS / GBM), 256, GEMM_SMEM>>>(
        ahi, alo, wqh, wql, bqkv, qkv, QKV_N);

    // 2) windowed causal attention -> att
    attn_kernel<<<dim3(WINDOW / TQ, NB, BATCH * N_HEADS), 256, ATTN_SMEM>>>(qkv, att);

    // att -> hi/lo (reuse buffers)
    {
        const int n4 = ROWS * D_MODEL / 4;
        split_hilo<<<(n4 + 255) / 256, 256>>>(att, ahi, alo, n4);
    }
    // 3) output projection (mma.sync split-bf16): out = att @ W_out + b_out
    gemm_mma_kernel<<<dim3(D_MODEL / GBN, ROWS / GBM), 256, GEMM_SMEM>>>(
        ahi, alo, woh, wol, bout, out, D_MODEL);
}

// round 4
// speedup vs baseline: 2.8117x; 1.3208x over previous
#include <cuda_runtime.h>
#include <cuda_bf16.h>
#include <cstdint>
#include <cstddef>

// Problem constants
#define D_MODEL 2048
#define N_HEADS 16
#define D_HEAD  128
#define WINDOW  512
#define BATCH   2
#define SEQ     4096
#define NB      (SEQ / WINDOW)
#define ROWS    (BATCH * SEQ)         // 8192
#define QKV_N   (3 * D_MODEL)         // 6144
#define KDIM    D_MODEL               // 2048
#define SCALE_F 0.08838834764831845f
#define LOG2E_F 1.4426950408889634f

// ---------------------------------------------------------------------------
// Scratch (__device__ globals; no allocation allowed)
// ---------------------------------------------------------------------------
__device__ float          g_qkv[(size_t)ROWS * QKV_N];
__device__ __nv_bfloat16  g_ahi[(size_t)ROWS * KDIM];
__device__ __nv_bfloat16  g_alo[(size_t)ROWS * KDIM];
__device__ __nv_bfloat16  g_wqkv_hi[(size_t)QKV_N * KDIM];
__device__ __nv_bfloat16  g_wqkv_lo[(size_t)QKV_N * KDIM];
__device__ __nv_bfloat16  g_wout_hi[(size_t)D_MODEL * KDIM];
__device__ __nv_bfloat16  g_wout_lo[(size_t)D_MODEL * KDIM];

// ---------------------------------------------------------------------------
// Baseline-ISA helpers (NO tcgen05 — ptxas target is compute_103)
// ---------------------------------------------------------------------------
__device__ __forceinline__ uint32_t smem_u32(const void* p) {
    uint32_t a;
    asm("{ .reg .u64 t; cvta.to.shared.u64 t, %1; cvt.u32.u64 %0, t; }" : "=r"(a) : "l"(p));
    return a;
}
#define CP_ASYNC16(dst, src) \
    asm volatile("cp.async.cg.shared.global [%0], [%1], 16;" :: "r"(dst), "l"(src))
#define CP_COMMIT()   asm volatile("cp.async.commit_group;" ::: "memory")
#define CP_WAITG(n)   asm volatile("cp.async.wait_group %0;" :: "n"(n) : "memory")

__device__ __forceinline__ void ldmx4(uint32_t* r, uint32_t addr) {
    asm volatile("ldmatrix.sync.aligned.m8n8.x4.shared.b16 {%0,%1,%2,%3}, [%4];"
                 : "=r"(r[0]), "=r"(r[1]), "=r"(r[2]), "=r"(r[3]) : "r"(addr));
}
__device__ __forceinline__ void ldmx4t(uint32_t* r, uint32_t addr) {
    asm volatile("ldmatrix.sync.aligned.m8n8.x4.trans.shared.b16 {%0,%1,%2,%3}, [%4];"
                 : "=r"(r[0]), "=r"(r[1]), "=r"(r[2]), "=r"(r[3]) : "r"(addr));
}
__device__ __forceinline__ void mma_bf16(float* d, const uint32_t* a, const uint32_t* b) {
    asm volatile("mma.sync.aligned.m16n8k16.row.col.f32.bf16.bf16.f32 "
                 "{%0,%1,%2,%3}, {%4,%5,%6,%7}, {%8,%9}, {%0,%1,%2,%3};"
                 : "+f"(d[0]), "+f"(d[1]), "+f"(d[2]), "+f"(d[3])
                 : "r"(a[0]), "r"(a[1]), "r"(a[2]), "r"(a[3]), "r"(b[0]), "r"(b[1]));
}
__device__ __forceinline__ uint32_t pack2(float a, float b) {
    __nv_bfloat162 t = __floats2bfloat162_rn(a, b);
    return *(uint32_t*)&t;
}
__device__ __forceinline__ void split2(float a, float b, uint32_t& h, uint32_t& l) {
    __nv_bfloat16 ha = __float2bfloat16(a), hb = __float2bfloat16(b);
    __nv_bfloat162 hv(ha, hb);
    __nv_bfloat162 lv(__float2bfloat16(a - __bfloat162float(ha)),
                      __float2bfloat16(b - __bfloat162float(hb)));
    h = *(uint32_t*)&hv; l = *(uint32_t*)&lv;
}

// ---------------------------------------------------------------------------
// Conversion kernels
// ---------------------------------------------------------------------------
__global__ void split_hilo(const float* __restrict__ in, __nv_bfloat16* __restrict__ hi,
                           __nv_bfloat16* __restrict__ lo, int n4)
{
    int i = blockIdx.x * blockDim.x + threadIdx.x;
    if (i >= n4) return;
    float4 v = ((const float4*)in)[i];
    uint32_t h0, l0, h1, l1;
    split2(v.x, v.y, h0, l0);
    split2(v.z, v.w, h1, l1);
    ((uint32_t*)hi)[i * 2]     = h0;
    ((uint32_t*)hi)[i * 2 + 1] = h1;
    ((uint32_t*)lo)[i * 2]     = l0;
    ((uint32_t*)lo)[i * 2 + 1] = l1;
}

// W[K,N] fp32 -> Wt hi/lo [N,K] bf16 (transpose + split)
__global__ void transpose_split(const float* __restrict__ W, __nv_bfloat16* __restrict__ hi,
                                __nv_bfloat16* __restrict__ lo, int K, int N)
{
    __shared__ float t[32][33];
    const int n0 = blockIdx.x * 32, k0 = blockIdx.y * 32;
    const int tx = threadIdx.x, ty = threadIdx.y;
    #pragma unroll
    for (int i = 0; i < 4; i++)
        t[ty + i * 8][tx] = W[(size_t)(k0 + ty + i * 8) * N + n0 + tx];
    __syncthreads();
    #pragma unroll
    for (int i = 0; i < 4; i++) {
        float v = t[tx][ty + i * 8];
        size_t o = (size_t)(n0 + ty + i * 8) * K + k0 + tx;
        __nv_bfloat16 h = __float2bfloat16(v);
        hi[o] = h;
        lo[o] = __float2bfloat16(v - __bfloat162float(h));
    }
}

// ---------------------------------------------------------------------------
// mma.sync split-bf16 GEMM, 3-stage cp.async pipeline.
//   C[M,N] = A @ Wt^T + bias.  CTA 128x128, 8 warps (64x32 each), BK=32.
// ---------------------------------------------------------------------------
#define GBM 128
#define GBN 128
#define GBK 32
#define LDT 40
#define BUF_B (128 * LDT * 2)         // 10240 B
#define STAGE_B (4 * BUF_B)           // 40960 B
#define NSTAGE 3
#define GEMM_SMEM (NSTAGE * STAGE_B)  // 122880 B

__device__ __forceinline__ void load_stage(
    uint32_t sb, uint32_t stage,
    const __nv_bfloat16* __restrict__ ahi, const __nv_bfloat16* __restrict__ alo,
    const __nv_bfloat16* __restrict__ bhi, const __nv_bfloat16* __restrict__ blo,
    int bm, int bn, int k0, int tid)
{
    #pragma unroll
    for (int it = 0; it < 8; it++) {
        const int c = tid + it * 256;
        const int buf = c >> 9;
        const int row = (c >> 2) & 127;
        const int kc = c & 3;
        const __nv_bfloat16* src;
        int grow;
        if (buf == 0)      { src = ahi; grow = bm + row; }
        else if (buf == 1) { src = alo; grow = bm + row; }
        else if (buf == 2) { src = bhi; grow = bn + row; }
        else               { src = blo; grow = bn + row; }
        const uint32_t dst = sb + stage + buf * BUF_B + row * (LDT * 2) + kc * 16;
        CP_ASYNC16(dst, src + (size_t)grow * KDIM + k0 + kc * 8);
    }
}

__global__ __launch_bounds__(256, 1)
void gemm_mma_kernel(const __nv_bfloat16* __restrict__ ahi, const __nv_bfloat16* __restrict__ alo,
                     const __nv_bfloat16* __restrict__ bhi, const __nv_bfloat16* __restrict__ blo,
                     const float* __restrict__ bias, float* __restrict__ C, int N)
{
    extern __shared__ char smem[];
    const uint32_t sb = smem_u32(smem);
    const int tid = threadIdx.x;
    const int wid = tid >> 5;
    const int lane = tid & 31;
    const int bm = blockIdx.y * GBM;
    const int bn = blockIdx.x * GBN;
    const int warp_m = (wid >> 2) * 64;
    const int warp_n = (wid & 3) * 32;

    float d[4][4][4];
    #pragma unroll
    for (int i = 0; i < 4; i++)
        #pragma unroll
        for (int j = 0; j < 4; j++)
            #pragma unroll
            for (int r = 0; r < 4; r++) d[i][j][r] = 0.0f;

    const int nk = KDIM / GBK;  // 64

    #pragma unroll
    for (int s = 0; s < NSTAGE; s++) {
        load_stage(sb, s * STAGE_B, ahi, alo, bhi, blo, bm, bn, s * GBK, tid);
        CP_COMMIT();
    }
    CP_WAITG(2);            // stage 0 landed
    __syncthreads();

    for (int kt = 0; kt < nk; kt++) {
        const uint32_t stage = (uint32_t)(kt % NSTAGE) * STAGE_B;

        #pragma unroll
        for (int k16 = 0; k16 < 2; k16++) {
            uint32_t ra[2][4][4];
            uint32_t rb[2][2][4];
            #pragma unroll
            for (int hl = 0; hl < 2; hl++) {
                const uint32_t abase = sb + stage + hl * BUF_B;
                #pragma unroll
                for (int mf = 0; mf < 4; mf++) {
                    const int row = warp_m + mf * 16 + (lane & 15);
                    const int col = ((lane >> 4) << 3) + k16 * 16;
                    ldmx4(ra[hl][mf], abase + row * (LDT * 2) + col * 2);
                }
                const uint32_t bbase = sb + stage + (2 + hl) * BUF_B;
                #pragma unroll
                for (int nf2 = 0; nf2 < 2; nf2++) {
                    const int row = warp_n + nf2 * 16 + ((lane >> 4) << 3) + (lane & 7);
                    const int col = (((lane >> 3) & 1) << 3) + k16 * 16;
                    ldmx4(rb[hl][nf2], bbase + row * (LDT * 2) + col * 2);
                }
            }
            #pragma unroll
            for (int t = 0; t < 3; t++) {
                const int ah = (t == 2) ? 1 : 0;
                const int bh = (t == 1) ? 1 : 0;
                #pragma unroll
                for (int mf = 0; mf < 4; mf++)
                    #pragma unroll
                    for (int nf = 0; nf < 4; nf++)
                        mma_bf16(d[mf][nf], ra[ah][mf], &rb[bh][nf >> 1][(nf & 1) * 2]);
            }
        }

        __syncthreads();
        if (kt + NSTAGE < nk)
            load_stage(sb, stage, ahi, alo, bhi, blo, bm, bn, (kt + NSTAGE) * GBK, tid);
        CP_COMMIT();
        CP_WAITG(2);        // next stage landed
        __syncthreads();
    }

    #pragma unroll
    for (int nf = 0; nf < 4; nf++) {
        const int c0 = bn + warp_n + nf * 8 + (lane & 3) * 2;
        const float b0 = bias[c0], b1 = bias[c0 + 1];
        #pragma unroll
        for (int mf = 0; mf < 4; mf++) {
            const int r0 = bm + warp_m + mf * 16 + (lane >> 2);
            float2 v0, v1;
            v0.x = d[mf][nf][0] + b0; v0.y = d[mf][nf][1] + b1;
            v1.x = d[mf][nf][2] + b0; v1.y = d[mf][nf][3] + b1;
            *(float2*)&C[(size_t)r0 * N + c0]       = v0;
            *(float2*)&C[(size_t)(r0 + 8) * N + c0] = v1;
        }
    }
}

// ---------------------------------------------------------------------------
// Tensor-core windowed causal flash attention (3-term split-bf16).
//   Block = 64 q-rows of one (b,h,window). 4 warps, each m16 x n64.
//   S = QK^T uses same frag patterns as the GEMM (K tile is [N,K] row-major).
//   P@V: S-accum -> A-frag register repack; V via ldmatrix.x4.trans.
//   Output written directly as bf16 hi/lo into out-proj A buffers.
// ---------------------------------------------------------------------------
#define SQE 136                 // padded row stride (bf16 elems); 272 B (16B mult)
#define SQB (SQE * 2)
#define ATILE_B (64 * SQB)      // 17408 B
#define ATTN_SMEM (4 * ATILE_B) // Qhi,Qlo,KVhi,KVlo = 69632 B

// load 64x128 fp32 tile (row stride QKV_N) -> bf16 hi/lo smem tiles
__device__ __forceinline__ void load_conv(char* hi, char* lo, const float* __restrict__ src)
{
    const int tid = threadIdx.x;
    #pragma unroll
    for (int it = 0; it < 16; it++) {
        const int lin = tid + it * 128;
        const int r = lin >> 5;
        const int c = (lin & 31) * 4;
        float4 v = *(const float4*)&src[(size_t)r * QKV_N + c];
        uint32_t h0, l0, h1, l1;
        split2(v.x, v.y, h0, l0);
        split2(v.z, v.w, h1, l1);
        const int byte = r * SQB + c * 2;
        *(uint32_t*)(hi + byte)     = h0;
        *(uint32_t*)(hi + byte + 4) = h1;
        *(uint32_t*)(lo + byte)     = l0;
        *(uint32_t*)(lo + byte + 4) = l1;
    }
}

__global__ __launch_bounds__(128)
void attn_mma_kernel(const float* __restrict__ qkv,
                     __nv_bfloat16* __restrict__ ohi, __nv_bfloat16* __restrict__ olo)
{
    extern __shared__ char asmem[];
    char* QHI = asmem;
    char* QLO = asmem + ATILE_B;
    char* KVH = asmem + 2 * ATILE_B;
    char* KVL = asmem + 3 * ATILE_B;
    const uint32_t sb = smem_u32(asmem);
    const uint32_t KVH_U = sb + 2 * ATILE_B;
    const uint32_t KVL_U = sb + 3 * ATILE_B;

    const int tid = threadIdx.x;
    const int wid = tid >> 5;           // 0..3
    const int lane = tid & 31;
    const int qb = blockIdx.x;          // 0..7
    const int n  = blockIdx.y;
    const int bh = blockIdx.z;
    const int b  = bh >> 4;
    const int h  = bh & 15;

    const size_t row0 = (size_t)b * SEQ + (size_t)n * WINDOW;
    const float* qptr = qkv + (row0 + qb * 64) * QKV_N + h * D_HEAD;
    const float* kbase = qkv + row0 * QKV_N + h * D_HEAD + D_MODEL;
    const float* vbase = qkv + row0 * QKV_N + h * D_HEAD + 2 * D_MODEL;

    load_conv(QHI, QLO, qptr);          // Q loaded once

    const int warp_m = wid * 16;
    const int r0 = lane >> 2;           // row within 8
    const int qq = lane & 3;

    float o[16][4];
    #pragma unroll
    for (int j = 0; j < 16; j++)
        #pragma unroll
        for (int r = 0; r < 4; r++) o[j][r] = 0.0f;
    float m0 = -1e30f, m1 = -1e30f, l0 = 0.0f, l1 = 0.0f;

    for (int jt = 0; jt <= qb; jt++) {
        __syncthreads();
        load_conv(KVH, KVL, kbase + (size_t)(jt * 64) * QKV_N);
        __syncthreads();

        // ---- S = Q K^T : 8 n8-tiles per warp ----
        float s[8][4];
        #pragma unroll
        for (int j = 0; j < 8; j++)
            #pragma unroll
            for (int r = 0; r < 4; r++) s[j][r] = 0.0f;

        #pragma unroll
        for (int k16 = 0; k16 < 8; k16++) {
            uint32_t ra[2][4], rb[2][4][4];
            #pragma unroll
            for (int hl = 0; hl < 2; hl++) {
                const uint32_t ab = sb + (hl ? ATILE_B : 0u);
                ldmx4(ra[hl], ab + (warp_m + (lane & 15)) * SQB
                                 + (((lane >> 4) << 3) + k16 * 16) * 2);
                const uint32_t bb = hl ? KVL_U : KVH_U;
                #pragma unroll
                for (int g = 0; g < 4; g++) {
                    const int row = g * 16 + ((lane >> 4) << 3) + (lane & 7);
                    const int col = (((lane >> 3) & 1) << 3) + k16 * 16;
                    ldmx4(rb[hl][g], bb + row * SQB + col * 2);
                }
            }
            #pragma unroll
            for (int t = 0; t < 3; t++) {
                const int ah = (t == 2) ? 1 : 0;
                const int bl = (t == 1) ? 1 : 0;
                #pragma unroll
                for (int j = 0; j < 8; j++)
                    mma_bf16(s[j], ra[ah], &rb[bl][j >> 1][(j & 1) * 2]);
            }
        }

        // ---- scale + causal mask (only diagonal tile masks) ----
        const int rg0 = warp_m + r0;        // row within 64-tile
        #pragma unroll
        for (int j = 0; j < 8; j++)
            #pragma unroll
            for (int r = 0; r < 4; r++) s[j][r] *= SCALE_F;
        if (jt == qb) {
            #pragma unroll
            for (int j = 0; j < 8; j++) {
                const int c0 = j * 8 + qq * 2;
                if (c0     > rg0)     s[j][0] = -1e30f;
                if (c0 + 1 > rg0)     s[j][1] = -1e30f;
                if (c0     > rg0 + 8) s[j][2] = -1e30f;
                if (c0 + 1 > rg0 + 8) s[j][3] = -1e30f;
            }
        }

        // ---- online softmax (rows r0, r0+8) ----
        float mx0 = -1e30f, mx1 = -1e30f;
        #pragma unroll
        for (int j = 0; j < 8; j++) {
            mx0 = fmaxf(mx0, fmaxf(s[j][0], s[j][1]));
            mx1 = fmaxf(mx1, fmaxf(s[j][2], s[j][3]));
        }
        #pragma unroll
        for (int off = 1; off < 4; off <<= 1) {
            mx0 = fmaxf(mx0, __shfl_xor_sync(0xffffffffu, mx0, off));
            mx1 = fmaxf(mx1, __shfl_xor_sync(0xffffffffu, mx1, off));
        }
        const float mn0 = fmaxf(m0, mx0), mn1 = fmaxf(m1, mx1);
        const float f0 = exp2f((m0 - mn0) * LOG2E_F);
        const float f1 = exp2f((m1 - mn1) * LOG2E_F);
        float rs0 = 0.0f, rs1 = 0.0f;
        #pragma unroll
        for (int j = 0; j < 8; j++) {
            s[j][0] = exp2f((s[j][0] - mn0) * LOG2E_F); rs0 += s[j][0];
            s[j][1] = exp2f((s[j][1] - mn0) * LOG2E_F); rs0 += s[j][1];
            s[j][2] = exp2f((s[j][2] - mn1) * LOG2E_F); rs1 += s[j][2];
            s[j][3] = exp2f((s[j][3] - mn1) * LOG2E_F); rs1 += s[j][3];
        }
        #pragma unroll
        for (int off = 1; off < 4; off <<= 1) {
            rs0 += __shfl_xor_sync(0xffffffffu, rs0, off);
            rs1 += __shfl_xor_sync(0xffffffffu, rs1, off);
        }
        l0 = l0 * f0 + rs0; m0 = mn0;
        l1 = l1 * f1 + rs1; m1 = mn1;
        #pragma unroll
        for (int j = 0; j < 16; j++) {
            o[j][0] *= f0; o[j][1] *= f0;
            o[j][2] *= f1; o[j][3] *= f1;
        }

        // ---- pack P into A-frags (hi/lo) ----
        uint32_t pah[4][4], pal[4][4];
        #pragma unroll
        for (int kc = 0; kc < 4; kc++) {
            split2(s[2 * kc][0],     s[2 * kc][1],     pah[kc][0], pal[kc][0]);
            split2(s[2 * kc][2],     s[2 * kc][3],     pah[kc][1], pal[kc][1]);
            split2(s[2 * kc + 1][0], s[2 * kc + 1][1], pah[kc][2], pal[kc][2]);
            split2(s[2 * kc + 1][2], s[2 * kc + 1][3], pah[kc][3], pal[kc][3]);
        }

        __syncthreads();
        load_conv(KVH, KVL, vbase + (size_t)(jt * 64) * QKV_N);
        __syncthreads();

        // ---- O += P V  (V [k=64][d=128], B-frags via ldmatrix.trans) ----
        const int vrow_part = ((lane >> 3) & 1) * 8 + (lane & 7);
        const int vcol_part = (lane >> 4) * 8;
        #pragma unroll
        for (int kc = 0; kc < 4; kc++) {
            #pragma unroll
            for (int d16 = 0; d16 < 8; d16++) {
                uint32_t vh[4], vl[4];
                const uint32_t off = (kc * 16 + vrow_part) * SQB + (d16 * 16 + vcol_part) * 2;
                ldmx4t(vh, KVH_U + off);
                ldmx4t(vl, KVL_U + off);
                mma_bf16(o[2 * d16],     pah[kc], &vh[0]);
                mma_bf16(o[2 * d16 + 1], pah[kc], &vh[2]);
                mma_bf16(o[2 * d16],     pah[kc], &vl[0]);
                mma_bf16(o[2 * d16 + 1], pah[kc], &vl[2]);
                mma_bf16(o[2 * d16],     pal[kc], &vh[0]);
                mma_bf16(o[2 * d16 + 1], pal[kc], &vh[2]);
            }
        }
    }

    // ---- epilogue: normalize, write bf16 hi/lo directly (out-proj A) ----
    const float inv0 = 1.0f / l0, inv1 = 1.0f / l1;
    const size_t gr0 = row0 + qb * 64 + warp_m + r0;
    const size_t gr1 = gr0 + 8;
    #pragma unroll
    for (int j = 0; j < 16; j++) {
        const int col = h * D_HEAD + j * 8 + qq * 2;
        uint32_t h0, lo0, h1, lo1;
        split2(o[j][0] * inv0, o[j][1] * inv0, h0, lo0);
        split2(o[j][2] * inv1, o[j][3] * inv1, h1, lo1);
        *(uint32_t*)&ohi[gr0 * KDIM + col] = h0;
        *(uint32_t*)&olo[gr0 * KDIM + col] = lo0;
        *(uint32_t*)&ohi[gr1 * KDIM + col] = h1;
        *(uint32_t*)&olo[gr1 * KDIM + col] = lo1;
    }
}

// ---------------------------------------------------------------------------
extern "C" void kernel_launch(void* const* d_in, const int* in_sizes, int n_in,
                              void* d_out, int out_size)
{
    const float* x    = (const float*)d_in[0];
    const float* Wqkv = (const float*)d_in[1];
    const float* bqkv = (const float*)d_in[2];
    const float* Wout = (const float*)d_in[3];
    const float* bout = (const float*)d_in[4];
    float* out = (float*)d_out;

    float* qkv;
    __nv_bfloat16 *ahi, *alo, *wqh, *wql, *woh, *wol;
    cudaGetSymbolAddress((void**)&qkv, g_qkv);
    cudaGetSymbolAddress((void**)&ahi, g_ahi);
    cudaGetSymbolAddress((void**)&alo, g_alo);
    cudaGetSymbolAddress((void**)&wqh, g_wqkv_hi);
    cudaGetSymbolAddress((void**)&wql, g_wqkv_lo);
    cudaGetSymbolAddress((void**)&woh, g_wout_hi);
    cudaGetSymbolAddress((void**)&wol, g_wout_lo);

    cudaFuncSetAttribute(gemm_mma_kernel,
                         cudaFuncAttributeMaxDynamicSharedMemorySize, GEMM_SMEM);
    cudaFuncSetAttribute(attn_mma_kernel,
                         cudaFuncAttributeMaxDynamicSharedMemorySize, ATTN_SMEM);

    // weight conversions
    transpose_split<<<dim3(QKV_N / 32, KDIM / 32), dim3(32, 8)>>>(Wqkv, wqh, wql, KDIM, QKV_N);
    transpose_split<<<dim3(D_MODEL / 32, KDIM / 32), dim3(32, 8)>>>(Wout, woh, wol, KDIM, D_MODEL);

    // x -> hi/lo
    {
        const int n4 = ROWS * D_MODEL / 4;
        split_hilo<<<(n4 + 255) / 256, 256>>>(x, ahi, alo, n4);
    }
    // 1) QKV projection
    gemm_mma_kernel<<<dim3(QKV_N / GBN, ROWS / GBM), 256, GEMM_SMEM>>>(
        ahi, alo, wqh, wql, bqkv, qkv, QKV_N);

    // 2) attention (writes hi/lo of att directly into A buffers)
    attn_mma_kernel<<<dim3(WINDOW / 64, NB, BATCH * N_HEADS), 128, ATTN_SMEM>>>(qkv, ahi, alo);

    // 3) output projection
    gemm_mma_kernel<<<dim3(D_MODEL / GBN, ROWS / GBM), 256, GEMM_SMEM>>>(
        ahi, alo, woh, wol, bout, out, D_MODEL);
}